// round 2
// baseline (speedup 1.0000x reference)
#include <cuda_runtime.h>
#include <cuda_bf16.h>
#include <cstdint>

#define BETA_F   0.9355f
#define T_STEPS  100
#define BATCH    8192
#define NIN      512
#define HID      512
#define NOUT     128

// ---------------------------------------------------------------------------
// Persistent device state (allowed: __device__ globals, no allocation)
// ---------------------------------------------------------------------------
__device__ alignas(128) __nv_bfloat16 g_W2hi[HID * HID];
__device__ alignas(128) __nv_bfloat16 g_W2lo[HID * HID];
__device__ alignas(128) __nv_bfloat16 g_W3hi[NOUT * HID];
__device__ alignas(128) __nv_bfloat16 g_W3lo[NOUT * HID];
__device__ alignas(128) float g_z1[BATCH * HID];
__device__ alignas(128) float g_m1[BATCH * HID];
__device__ alignas(128) float g_m2[BATCH * HID];

// ---------------------------------------------------------------------------
// PTX helpers
// ---------------------------------------------------------------------------
__device__ __forceinline__ void cp_async16(void* dst, const void* src) {
    uint32_t s = (uint32_t)__cvta_generic_to_shared(dst);
    asm volatile("cp.async.cg.shared.global [%0], [%1], 16;\n" :: "r"(s), "l"(src) : "memory");
}
__device__ __forceinline__ void cp_commit() {
    asm volatile("cp.async.commit_group;\n" ::: "memory");
}
template <int N>
__device__ __forceinline__ void cp_wait() {
    asm volatile("cp.async.wait_group %0;\n" :: "n"(N) : "memory");
}

// mma.sync m16n8k16, bf16 x bf16 -> f32 accumulate
__device__ __forceinline__ void mma_bf16(float* c,
                                         uint32_t a0, uint32_t a1, uint32_t a2, uint32_t a3,
                                         uint32_t b0, uint32_t b1) {
    asm volatile(
        "mma.sync.aligned.m16n8k16.row.col.f32.bf16.bf16.f32 "
        "{%0,%1,%2,%3}, {%4,%5,%6,%7}, {%8,%9}, {%0,%1,%2,%3};\n"
        : "+f"(c[0]), "+f"(c[1]), "+f"(c[2]), "+f"(c[3])
        : "r"(a0), "r"(a1), "r"(a2), "r"(a3), "r"(b0), "r"(b1));
}

// ---------------------------------------------------------------------------
// Kernel 1: split W2/W3 into exact bf16 hi+lo pairs
// ---------------------------------------------------------------------------
__global__ void prep_kernel(const float* __restrict__ W2, const float* __restrict__ W3) {
    int i = blockIdx.x * blockDim.x + threadIdx.x;
    const int n2 = HID * HID;
    const int n3 = NOUT * HID;
    if (i < n2) {
        float w = W2[i];
        __nv_bfloat16 h = __float2bfloat16(w);
        g_W2hi[i] = h;
        g_W2lo[i] = __float2bfloat16(w - __bfloat162float(h));
    } else if (i < n2 + n3) {
        int j = i - n2;
        float w = W3[j];
        __nv_bfloat16 h = __float2bfloat16(w);
        g_W3hi[j] = h;
        g_W3lo[j] = __float2bfloat16(w - __bfloat162float(h));
    }
}

// ---------------------------------------------------------------------------
// Kernel 2: z1 = x @ W1^T + b1   (fp32 SIMT tiled GEMM, one-time cost)
// ---------------------------------------------------------------------------
__global__ void __launch_bounds__(256) z1_kernel(const float* __restrict__ x,
                                                 const float* __restrict__ W1,
                                                 const float* __restrict__ b1) {
    __shared__ float Xs[16][68];
    __shared__ float Ws[16][68];
    const int tid = threadIdx.x;
    const int bm = blockIdx.y * 64;   // batch tile
    const int bn = blockIdx.x * 64;   // hidden tile
    const int tx = tid & 15, ty = tid >> 4;
    const int lrow = tid >> 2;        // 0..63
    const int lk = (tid & 3) * 4;     // 0,4,8,12

    float c[4][4] = {};

    for (int k0 = 0; k0 < NIN; k0 += 16) {
        float4 xa = *(const float4*)(x  + (size_t)(bm + lrow) * NIN + k0 + lk);
        float4 wa = *(const float4*)(W1 + (size_t)(bn + lrow) * NIN + k0 + lk);
        __syncthreads();
        Xs[lk + 0][lrow] = xa.x; Xs[lk + 1][lrow] = xa.y;
        Xs[lk + 2][lrow] = xa.z; Xs[lk + 3][lrow] = xa.w;
        Ws[lk + 0][lrow] = wa.x; Ws[lk + 1][lrow] = wa.y;
        Ws[lk + 2][lrow] = wa.z; Ws[lk + 3][lrow] = wa.w;
        __syncthreads();
        #pragma unroll
        for (int k = 0; k < 16; ++k) {
            float a[4], b[4];
            #pragma unroll
            for (int i = 0; i < 4; ++i) a[i] = Xs[k][ty * 4 + i];
            #pragma unroll
            for (int j = 0; j < 4; ++j) b[j] = Ws[k][tx * 4 + j];
            #pragma unroll
            for (int i = 0; i < 4; ++i)
                #pragma unroll
                for (int j = 0; j < 4; ++j)
                    c[i][j] += a[i] * b[j];
        }
    }
    #pragma unroll
    for (int i = 0; i < 4; ++i)
        #pragma unroll
        for (int j = 0; j < 4; ++j)
            g_z1[(size_t)(bm + ty * 4 + i) * HID + bn + tx * 4 + j] = c[i][j] + b1[bn + tx * 4 + j];
}

// ---------------------------------------------------------------------------
// Kernel 3: persistent fused SNN kernel.
// grid = 128 CTAs (one 64-row batch tile each), 256 threads, runs all T steps.
//
// SMEM map (bytes):
//   s1   bf16 [64][520]                      @      0   (66560)
//   wb   bf16 [2 buf][2 hi/lo][128][72]      @  66560   (73728)
//   s2   bf16 [64][132]                      @ 140288   (16896)
//   w3t  bf16 [2 hi/lo][128][136]            @ 157184   (69632)
//   total 226816
// ---------------------------------------------------------------------------
#define S1_STR  520
#define WB_STR  72
#define S2_STR  132
#define W3_STR  136
#define SMEM_TOTAL 226816

__global__ void __launch_bounds__(256, 1) snn_kernel(const float* __restrict__ b2,
                                                     const float* __restrict__ b3,
                                                     float* __restrict__ out) {
    extern __shared__ char smem[];
    __nv_bfloat16* s1  = (__nv_bfloat16*)(smem);
    __nv_bfloat16* wb  = (__nv_bfloat16*)(smem + 66560);
    __nv_bfloat16* s2  = (__nv_bfloat16*)(smem + 140288);
    __nv_bfloat16* w3t = (__nv_bfloat16*)(smem + 157184);

    const int tid  = threadIdx.x;
    const int lane = tid & 31;
    const int warp = tid >> 5;
    const int wm = warp & 3;      // 4 warps over M (16 rows each)
    const int wn = warp >> 2;     // 2 warps over N (64 cols each)
    const int g  = lane >> 2;     // 0..7
    const int t  = lane & 3;      // 0..3
    const int row0 = blockIdx.x * 64;

    // ---- zero membranes for this tile ----
    for (int i = tid; i < 64 * HID / 4; i += 256) {
        size_t gi = (size_t)row0 * HID + (size_t)i * 4;
        *(float4*)(g_m1 + gi) = make_float4(0.f, 0.f, 0.f, 0.f);
        *(float4*)(g_m2 + gi) = make_float4(0.f, 0.f, 0.f, 0.f);
    }
    __syncthreads();

    float acc3[8][4] = {};   // persistent GEMM3 accumulator (warp tile 16x64 of 64x128)

    #pragma unroll 1
    for (int tt = 0; tt < T_STEPS; ++tt) {
        // ======== Phase 1: LIF layer 1, write s1 (bf16 {0,1}) to SMEM ========
        #pragma unroll 4
        for (int i = 0; i < 32; ++i) {
            int l = i * 256 + tid;                 // float4 index, 0..8191
            size_t gi = (size_t)row0 * HID + (size_t)l * 4;
            float4 z = *(const float4*)(g_z1 + gi);
            float4 m = *(float4*)(g_m1 + gi);
            unsigned short sx, sy, sz, sw;
            m.x = BETA_F * m.x + z.x; if (m.x >= 1.0f) { m.x -= 1.0f; sx = 0x3F80; } else sx = 0;
            m.y = BETA_F * m.y + z.y; if (m.y >= 1.0f) { m.y -= 1.0f; sy = 0x3F80; } else sy = 0;
            m.z = BETA_F * m.z + z.z; if (m.z >= 1.0f) { m.z -= 1.0f; sz = 0x3F80; } else sz = 0;
            m.w = BETA_F * m.w + z.w; if (m.w >= 1.0f) { m.w -= 1.0f; sw = 0x3F80; } else sw = 0;
            *(float4*)(g_m1 + gi) = m;
            int lr = (l * 4) >> 9;                 // local row
            int lc = (l * 4) & 511;                // local col (mult of 4)
            *(uint2*)((char*)s1 + lr * (S1_STR * 2) + lc * 2) =
                make_uint2((uint32_t)sx | ((uint32_t)sy << 16),
                           (uint32_t)sz | ((uint32_t)sw << 16));
        }
        __syncthreads();

        // ======== Phase 2: 4 chunks of 128 hidden-2 columns ========
        #pragma unroll 1
        for (int c = 0; c < 4; ++c) {
            // prefetch this chunk's W3 slice (hi+lo) [128 o][128 k]
            {
                #pragma unroll
                for (int q = 0; q < 8; ++q) {
                    int lin = tid + q * 256;       // 0..2047
                    int o = lin >> 4, seg = (lin & 15) * 8;
                    cp_async16(w3t + o * W3_STR + seg,           g_W3hi + (size_t)o * HID + c * 128 + seg);
                    cp_async16(w3t + 128 * W3_STR + o * W3_STR + seg,
                               g_W3lo + (size_t)o * HID + c * 128 + seg);
                }
                cp_commit();
            }
            // prefetch W2 k-tile 0 (hi+lo) [128 n][64 k]
            {
                #pragma unroll
                for (int q = 0; q < 4; ++q) {
                    int lin = tid + q * 256;       // 0..1023
                    int n = lin >> 3, seg = (lin & 7) * 8;
                    cp_async16(wb + 0 * 9216 + n * WB_STR + seg,
                               g_W2hi + (size_t)(c * 128 + n) * HID + 0 + seg);
                    cp_async16(wb + 1 * 9216 + n * WB_STR + seg,
                               g_W2lo + (size_t)(c * 128 + n) * HID + 0 + seg);
                }
                cp_commit();
            }

            float accz[8][4] = {};

            // ---- GEMM2: z2_chunk = s1 @ W2hi^T + s1 @ W2lo^T ----
            #pragma unroll 1
            for (int kt = 0; kt < 8; ++kt) {
                const int cur = kt & 1;
                if (kt < 7) {
                    const int nxt = cur ^ 1;
                    #pragma unroll
                    for (int q = 0; q < 4; ++q) {
                        int lin = tid + q * 256;
                        int n = lin >> 3, seg = (lin & 7) * 8;
                        cp_async16(wb + (nxt * 2 + 0) * 9216 + n * WB_STR + seg,
                                   g_W2hi + (size_t)(c * 128 + n) * HID + (kt + 1) * 64 + seg);
                        cp_async16(wb + (nxt * 2 + 1) * 9216 + n * WB_STR + seg,
                                   g_W2lo + (size_t)(c * 128 + n) * HID + (kt + 1) * 64 + seg);
                    }
                    cp_commit();
                    cp_wait<1>();
                } else {
                    cp_wait<0>();
                }
                __syncthreads();

                const __nv_bfloat16* bh_base = wb + (cur * 2 + 0) * 9216 + (wn * 64 + g) * WB_STR + t * 2;
                const __nv_bfloat16* bl_base = bh_base + 9216;
                const __nv_bfloat16* ap_base = s1 + (wm * 16 + g) * S1_STR + kt * 64 + t * 2;

                #pragma unroll
                for (int kk = 0; kk < 64; kk += 16) {
                    const __nv_bfloat16* ap = ap_base + kk;
                    uint32_t a0 = *(const uint32_t*)(ap);
                    uint32_t a1 = *(const uint32_t*)(ap + 8 * S1_STR);
                    uint32_t a2 = *(const uint32_t*)(ap + 8);
                    uint32_t a3 = *(const uint32_t*)(ap + 8 * S1_STR + 8);
                    #pragma unroll
                    for (int nb = 0; nb < 8; ++nb) {
                        const __nv_bfloat16* bh = bh_base + nb * 8 * WB_STR + kk;
                        uint32_t b0 = *(const uint32_t*)(bh);
                        uint32_t b1 = *(const uint32_t*)(bh + 8);
                        mma_bf16(accz[nb], a0, a1, a2, a3, b0, b1);
                        const __nv_bfloat16* bl = bl_base + nb * 8 * WB_STR + kk;
                        uint32_t c0 = *(const uint32_t*)(bl);
                        uint32_t c1 = *(const uint32_t*)(bl + 8);
                        mma_bf16(accz[nb], a0, a1, a2, a3, c0, c1);
                    }
                }
                __syncthreads();
            }

            // ---- Epilogue: + b2, LIF layer 2, write s2 (bf16) to SMEM ----
            #pragma unroll
            for (int nb = 0; nb < 8; ++nb) {
                int lcol = wn * 64 + nb * 8 + t * 2;
                int jcol = c * 128 + lcol;
                float2 bb = *(const float2*)(b2 + jcol);
                #pragma unroll
                for (int h = 0; h < 2; ++h) {
                    int lr = wm * 16 + g + h * 8;
                    size_t mi = (size_t)(row0 + lr) * HID + jcol;
                    float2 m = *(float2*)(g_m2 + mi);
                    m.x = BETA_F * m.x + (accz[nb][h * 2 + 0] + bb.x);
                    m.y = BETA_F * m.y + (accz[nb][h * 2 + 1] + bb.y);
                    unsigned short sx, sy;
                    if (m.x >= 1.0f) { m.x -= 1.0f; sx = 0x3F80; } else sx = 0;
                    if (m.y >= 1.0f) { m.y -= 1.0f; sy = 0x3F80; } else sy = 0;
                    *(float2*)(g_m2 + mi) = m;
                    *(uint32_t*)((char*)s2 + lr * (S2_STR * 2) + lcol * 2) =
                        (uint32_t)sx | ((uint32_t)sy << 16);
                }
            }
            __syncthreads();

            // ---- GEMM3: acc3 += s2_chunk @ W3hi^T + s2_chunk @ W3lo^T ----
            {
                const __nv_bfloat16* ap_base = s2 + (wm * 16 + g) * S2_STR + t * 2;
                const __nv_bfloat16* bh_base = w3t + (wn * 64 + g) * W3_STR + t * 2;
                const __nv_bfloat16* bl_base = bh_base + 128 * W3_STR;
                #pragma unroll
                for (int kk = 0; kk < 128; kk += 16) {
                    const __nv_bfloat16* ap = ap_base + kk;
                    uint32_t a0 = *(const uint32_t*)(ap);
                    uint32_t a1 = *(const uint32_t*)(ap + 8 * S2_STR);
                    uint32_t a2 = *(const uint32_t*)(ap + 8);
                    uint32_t a3 = *(const uint32_t*)(ap + 8 * S2_STR + 8);
                    #pragma unroll
                    for (int nb = 0; nb < 8; ++nb) {
                        const __nv_bfloat16* bh = bh_base + nb * 8 * W3_STR + kk;
                        uint32_t b0 = *(const uint32_t*)(bh);
                        uint32_t b1 = *(const uint32_t*)(bh + 8);
                        mma_bf16(acc3[nb], a0, a1, a2, a3, b0, b1);
                        const __nv_bfloat16* bl = bl_base + nb * 8 * W3_STR + kk;
                        uint32_t c0 = *(const uint32_t*)(bl);
                        uint32_t c1 = *(const uint32_t*)(bl + 8);
                        mma_bf16(acc3[nb], a0, a1, a2, a3, c0, c1);
                    }
                }
            }
            __syncthreads();   // protect w3t/s2 before next chunk's prefetch
        } // chunks
    } // time steps

    // ======== Final output: out = acc/T + b3 ========
    #pragma unroll
    for (int nb = 0; nb < 8; ++nb) {
        int o = wn * 64 + nb * 8 + t * 2;
        float2 bb = *(const float2*)(b3 + o);
        #pragma unroll
        for (int h = 0; h < 2; ++h) {
            int r = row0 + wm * 16 + g + h * 8;
            float2 v;
            v.x = acc3[nb][h * 2 + 0] / (float)T_STEPS + bb.x;
            v.y = acc3[nb][h * 2 + 1] / (float)T_STEPS + bb.y;
            *(float2*)(out + (size_t)r * NOUT + o) = v;
        }
    }
}

// ---------------------------------------------------------------------------
// Launch
// ---------------------------------------------------------------------------
extern "C" void kernel_launch(void* const* d_in, const int* in_sizes, int n_in,
                              void* d_out, int out_size) {
    (void)in_sizes; (void)n_in; (void)out_size;
    const float* x  = (const float*)d_in[0];
    const float* W1 = (const float*)d_in[1];
    const float* b1 = (const float*)d_in[2];
    const float* W2 = (const float*)d_in[3];
    const float* b2 = (const float*)d_in[4];
    const float* W3 = (const float*)d_in[5];
    const float* b3 = (const float*)d_in[6];
    float* out = (float*)d_out;

    const int nconv = HID * HID + NOUT * HID;
    prep_kernel<<<(nconv + 255) / 256, 256>>>(W2, W3);

    dim3 zgrid(HID / 64, BATCH / 64);
    z1_kernel<<<zgrid, 256>>>(x, W1, b1);

    cudaFuncSetAttribute(snn_kernel, cudaFuncAttributeMaxDynamicSharedMemorySize, SMEM_TOTAL);
    snn_kernel<<<BATCH / 64, 256, SMEM_TOTAL>>>(b2, b3, out);
}

// round 3
// speedup vs baseline: 1.0042x; 1.0042x over previous
#include <cuda_runtime.h>
#include <cuda_bf16.h>
#include <cstdint>

#define BETA_F   0.9355f
#define T_STEPS  100
#define BATCH    8192
#define NIN      512
#define HID      512
#define NOUT     128

// ---------------------------------------------------------------------------
// Persistent device state (allowed: __device__ globals, no allocation)
// ---------------------------------------------------------------------------
__device__ alignas(128) __nv_bfloat16 g_W2hi[HID * HID];
__device__ alignas(128) __nv_bfloat16 g_W2lo[HID * HID];
__device__ alignas(128) __nv_bfloat16 g_W3hi[NOUT * HID];
__device__ alignas(128) __nv_bfloat16 g_W3lo[NOUT * HID];
__device__ alignas(128) float g_z1[BATCH * HID];
__device__ alignas(128) float g_m1[BATCH * HID];
__device__ alignas(128) float g_m2[BATCH * HID];

// ---------------------------------------------------------------------------
// PTX helpers
// ---------------------------------------------------------------------------
__device__ __forceinline__ void cp_async16(void* dst, const void* src) {
    uint32_t s = (uint32_t)__cvta_generic_to_shared(dst);
    asm volatile("cp.async.cg.shared.global [%0], [%1], 16;\n" :: "r"(s), "l"(src) : "memory");
}
__device__ __forceinline__ void cp_commit() {
    asm volatile("cp.async.commit_group;\n" ::: "memory");
}
template <int N>
__device__ __forceinline__ void cp_wait() {
    asm volatile("cp.async.wait_group %0;\n" :: "n"(N) : "memory");
}

// mma.sync m16n8k16, bf16 x bf16 -> f32 accumulate
__device__ __forceinline__ void mma_bf16(float* c,
                                         uint32_t a0, uint32_t a1, uint32_t a2, uint32_t a3,
                                         uint32_t b0, uint32_t b1) {
    asm volatile(
        "mma.sync.aligned.m16n8k16.row.col.f32.bf16.bf16.f32 "
        "{%0,%1,%2,%3}, {%4,%5,%6,%7}, {%8,%9}, {%0,%1,%2,%3};\n"
        : "+f"(c[0]), "+f"(c[1]), "+f"(c[2]), "+f"(c[3])
        : "r"(a0), "r"(a1), "r"(a2), "r"(a3), "r"(b0), "r"(b1));
}

// ---------------------------------------------------------------------------
// Kernel 1: split W2/W3 into exact bf16 hi+lo pairs
// ---------------------------------------------------------------------------
__global__ void prep_kernel(const float* __restrict__ W2, const float* __restrict__ W3) {
    int i = blockIdx.x * blockDim.x + threadIdx.x;
    const int n2 = HID * HID;
    const int n3 = NOUT * HID;
    if (i < n2) {
        float w = W2[i];
        __nv_bfloat16 h = __float2bfloat16(w);
        g_W2hi[i] = h;
        g_W2lo[i] = __float2bfloat16(w - __bfloat162float(h));
    } else if (i < n2 + n3) {
        int j = i - n2;
        float w = W3[j];
        __nv_bfloat16 h = __float2bfloat16(w);
        g_W3hi[j] = h;
        g_W3lo[j] = __float2bfloat16(w - __bfloat162float(h));
    }
}

// ---------------------------------------------------------------------------
// Kernel 2: z1 = x @ W1^T + b1   (fp32 SIMT tiled GEMM, one-time cost)
// ---------------------------------------------------------------------------
__global__ void __launch_bounds__(256) z1_kernel(const float* __restrict__ x,
                                                 const float* __restrict__ W1,
                                                 const float* __restrict__ b1) {
    __shared__ float Xs[16][68];
    __shared__ float Ws[16][68];
    const int tid = threadIdx.x;
    const int bm = blockIdx.y * 64;   // batch tile
    const int bn = blockIdx.x * 64;   // hidden tile
    const int tx = tid & 15, ty = tid >> 4;
    const int lrow = tid >> 2;        // 0..63
    const int lk = (tid & 3) * 4;     // 0,4,8,12

    float c[4][4] = {};

    for (int k0 = 0; k0 < NIN; k0 += 16) {
        float4 xa = *(const float4*)(x  + (size_t)(bm + lrow) * NIN + k0 + lk);
        float4 wa = *(const float4*)(W1 + (size_t)(bn + lrow) * NIN + k0 + lk);
        __syncthreads();
        Xs[lk + 0][lrow] = xa.x; Xs[lk + 1][lrow] = xa.y;
        Xs[lk + 2][lrow] = xa.z; Xs[lk + 3][lrow] = xa.w;
        Ws[lk + 0][lrow] = wa.x; Ws[lk + 1][lrow] = wa.y;
        Ws[lk + 2][lrow] = wa.z; Ws[lk + 3][lrow] = wa.w;
        __syncthreads();
        #pragma unroll
        for (int k = 0; k < 16; ++k) {
            float a[4], b[4];
            #pragma unroll
            for (int i = 0; i < 4; ++i) a[i] = Xs[k][ty * 4 + i];
            #pragma unroll
            for (int j = 0; j < 4; ++j) b[j] = Ws[k][tx * 4 + j];
            #pragma unroll
            for (int i = 0; i < 4; ++i)
                #pragma unroll
                for (int j = 0; j < 4; ++j)
                    c[i][j] += a[i] * b[j];
        }
    }
    #pragma unroll
    for (int i = 0; i < 4; ++i)
        #pragma unroll
        for (int j = 0; j < 4; ++j)
            g_z1[(size_t)(bm + ty * 4 + i) * HID + bn + tx * 4 + j] = c[i][j] + b1[bn + tx * 4 + j];
}

// ---------------------------------------------------------------------------
// Kernel 3: persistent fused SNN kernel.
// grid = 128 CTAs (one 64-row batch tile each), 256 threads, runs all T steps.
//
// SMEM map (bytes):
//   s1   bf16 [64][520]                      @      0   (66560)
//   wb   bf16 [2 buf][2 hi/lo][128][72]      @  66560   (73728)
//   s2   bf16 [64][132]                      @ 140288   (16896)
//   w3t  bf16 [2 hi/lo][128][136]            @ 157184   (69632)
//   total 226816
// ---------------------------------------------------------------------------
#define S1_STR  520
#define WB_STR  72
#define S2_STR  132
#define W3_STR  136
#define SMEM_TOTAL 226816

__global__ void __launch_bounds__(256, 1) snn_kernel(const float* __restrict__ b2,
                                                     const float* __restrict__ b3,
                                                     float* __restrict__ out) {
    extern __shared__ char smem[];
    __nv_bfloat16* s1  = (__nv_bfloat16*)(smem);
    __nv_bfloat16* wb  = (__nv_bfloat16*)(smem + 66560);
    __nv_bfloat16* s2  = (__nv_bfloat16*)(smem + 140288);
    __nv_bfloat16* w3t = (__nv_bfloat16*)(smem + 157184);

    const int tid  = threadIdx.x;
    const int lane = tid & 31;
    const int warp = tid >> 5;
    const int wm = warp & 3;      // 4 warps over M (16 rows each)
    const int wn = warp >> 2;     // 2 warps over N (64 cols each)
    const int g  = lane >> 2;     // 0..7
    const int t  = lane & 3;      // 0..3
    const int row0 = blockIdx.x * 64;

    // ---- zero membranes for this tile ----
    for (int i = tid; i < 64 * HID / 4; i += 256) {
        size_t gi = (size_t)row0 * HID + (size_t)i * 4;
        *(float4*)(g_m1 + gi) = make_float4(0.f, 0.f, 0.f, 0.f);
        *(float4*)(g_m2 + gi) = make_float4(0.f, 0.f, 0.f, 0.f);
    }
    __syncthreads();

    float acc3[8][4] = {};   // persistent GEMM3 accumulator (warp tile 16x64 of 64x128)

    #pragma unroll 1
    for (int tt = 0; tt < T_STEPS; ++tt) {
        // ======== Phase 1: LIF layer 1, write s1 (bf16 {0,1}) to SMEM ========
        #pragma unroll 4
        for (int i = 0; i < 32; ++i) {
            int l = i * 256 + tid;                 // float4 index, 0..8191
            size_t gi = (size_t)row0 * HID + (size_t)l * 4;
            float4 z = *(const float4*)(g_z1 + gi);
            float4 m = *(float4*)(g_m1 + gi);
            unsigned short sx, sy, sz, sw;
            m.x = BETA_F * m.x + z.x; if (m.x >= 1.0f) { m.x -= 1.0f; sx = 0x3F80; } else sx = 0;
            m.y = BETA_F * m.y + z.y; if (m.y >= 1.0f) { m.y -= 1.0f; sy = 0x3F80; } else sy = 0;
            m.z = BETA_F * m.z + z.z; if (m.z >= 1.0f) { m.z -= 1.0f; sz = 0x3F80; } else sz = 0;
            m.w = BETA_F * m.w + z.w; if (m.w >= 1.0f) { m.w -= 1.0f; sw = 0x3F80; } else sw = 0;
            *(float4*)(g_m1 + gi) = m;
            int lr = (l * 4) >> 9;                 // local row
            int lc = (l * 4) & 511;                // local col (mult of 4)
            *(uint2*)((char*)s1 + lr * (S1_STR * 2) + lc * 2) =
                make_uint2((uint32_t)sx | ((uint32_t)sy << 16),
                           (uint32_t)sz | ((uint32_t)sw << 16));
        }
        __syncthreads();

        // ======== Phase 2: 4 chunks of 128 hidden-2 columns ========
        #pragma unroll 1
        for (int c = 0; c < 4; ++c) {
            // prefetch this chunk's W3 slice (hi+lo) [128 o][128 k]
            {
                #pragma unroll
                for (int q = 0; q < 8; ++q) {
                    int lin = tid + q * 256;       // 0..2047
                    int o = lin >> 4, seg = (lin & 15) * 8;
                    cp_async16(w3t + o * W3_STR + seg,           g_W3hi + (size_t)o * HID + c * 128 + seg);
                    cp_async16(w3t + 128 * W3_STR + o * W3_STR + seg,
                               g_W3lo + (size_t)o * HID + c * 128 + seg);
                }
                cp_commit();
            }
            // prefetch W2 k-tile 0 (hi+lo) [128 n][64 k]
            {
                #pragma unroll
                for (int q = 0; q < 4; ++q) {
                    int lin = tid + q * 256;       // 0..1023
                    int n = lin >> 3, seg = (lin & 7) * 8;
                    cp_async16(wb + 0 * 9216 + n * WB_STR + seg,
                               g_W2hi + (size_t)(c * 128 + n) * HID + 0 + seg);
                    cp_async16(wb + 1 * 9216 + n * WB_STR + seg,
                               g_W2lo + (size_t)(c * 128 + n) * HID + 0 + seg);
                }
                cp_commit();
            }

            float accz[8][4] = {};

            // ---- GEMM2: z2_chunk = s1 @ W2hi^T + s1 @ W2lo^T ----
            #pragma unroll 1
            for (int kt = 0; kt < 8; ++kt) {
                const int cur = kt & 1;
                if (kt < 7) {
                    const int nxt = cur ^ 1;
                    #pragma unroll
                    for (int q = 0; q < 4; ++q) {
                        int lin = tid + q * 256;
                        int n = lin >> 3, seg = (lin & 7) * 8;
                        cp_async16(wb + (nxt * 2 + 0) * 9216 + n * WB_STR + seg,
                                   g_W2hi + (size_t)(c * 128 + n) * HID + (kt + 1) * 64 + seg);
                        cp_async16(wb + (nxt * 2 + 1) * 9216 + n * WB_STR + seg,
                                   g_W2lo + (size_t)(c * 128 + n) * HID + (kt + 1) * 64 + seg);
                    }
                    cp_commit();
                    cp_wait<1>();
                } else {
                    cp_wait<0>();
                }
                __syncthreads();

                const __nv_bfloat16* bh_base = wb + (cur * 2 + 0) * 9216 + (wn * 64 + g) * WB_STR + t * 2;
                const __nv_bfloat16* bl_base = bh_base + 9216;
                const __nv_bfloat16* ap_base = s1 + (wm * 16 + g) * S1_STR + kt * 64 + t * 2;

                #pragma unroll
                for (int kk = 0; kk < 64; kk += 16) {
                    const __nv_bfloat16* ap = ap_base + kk;
                    uint32_t a0 = *(const uint32_t*)(ap);
                    uint32_t a1 = *(const uint32_t*)(ap + 8 * S1_STR);
                    uint32_t a2 = *(const uint32_t*)(ap + 8);
                    uint32_t a3 = *(const uint32_t*)(ap + 8 * S1_STR + 8);
                    #pragma unroll
                    for (int nb = 0; nb < 8; ++nb) {
                        const __nv_bfloat16* bh = bh_base + nb * 8 * WB_STR + kk;
                        uint32_t b0 = *(const uint32_t*)(bh);
                        uint32_t b1 = *(const uint32_t*)(bh + 8);
                        mma_bf16(accz[nb], a0, a1, a2, a3, b0, b1);
                        const __nv_bfloat16* bl = bl_base + nb * 8 * WB_STR + kk;
                        uint32_t c0 = *(const uint32_t*)(bl);
                        uint32_t c1 = *(const uint32_t*)(bl + 8);
                        mma_bf16(accz[nb], a0, a1, a2, a3, c0, c1);
                    }
                }
                __syncthreads();
            }

            // ---- Epilogue: + b2, LIF layer 2, write s2 (bf16) to SMEM ----
            #pragma unroll
            for (int nb = 0; nb < 8; ++nb) {
                int lcol = wn * 64 + nb * 8 + t * 2;
                int jcol = c * 128 + lcol;
                float2 bb = *(const float2*)(b2 + jcol);
                #pragma unroll
                for (int h = 0; h < 2; ++h) {
                    int lr = wm * 16 + g + h * 8;
                    size_t mi = (size_t)(row0 + lr) * HID + jcol;
                    float2 m = *(float2*)(g_m2 + mi);
                    m.x = BETA_F * m.x + (accz[nb][h * 2 + 0] + bb.x);
                    m.y = BETA_F * m.y + (accz[nb][h * 2 + 1] + bb.y);
                    unsigned short sx, sy;
                    if (m.x >= 1.0f) { m.x -= 1.0f; sx = 0x3F80; } else sx = 0;
                    if (m.y >= 1.0f) { m.y -= 1.0f; sy = 0x3F80; } else sy = 0;
                    *(float2*)(g_m2 + mi) = m;
                    *(uint32_t*)((char*)s2 + lr * (S2_STR * 2) + lcol * 2) =
                        (uint32_t)sx | ((uint32_t)sy << 16);
                }
            }
            __syncthreads();

            // ---- GEMM3: acc3 += s2_chunk @ W3hi^T + s2_chunk @ W3lo^T ----
            {
                const __nv_bfloat16* ap_base = s2 + (wm * 16 + g) * S2_STR + t * 2;
                const __nv_bfloat16* bh_base = w3t + (wn * 64 + g) * W3_STR + t * 2;
                const __nv_bfloat16* bl_base = bh_base + 128 * W3_STR;
                #pragma unroll
                for (int kk = 0; kk < 128; kk += 16) {
                    const __nv_bfloat16* ap = ap_base + kk;
                    uint32_t a0 = *(const uint32_t*)(ap);
                    uint32_t a1 = *(const uint32_t*)(ap + 8 * S2_STR);
                    uint32_t a2 = *(const uint32_t*)(ap + 8);
                    uint32_t a3 = *(const uint32_t*)(ap + 8 * S2_STR + 8);
                    #pragma unroll
                    for (int nb = 0; nb < 8; ++nb) {
                        const __nv_bfloat16* bh = bh_base + nb * 8 * W3_STR + kk;
                        uint32_t b0 = *(const uint32_t*)(bh);
                        uint32_t b1 = *(const uint32_t*)(bh + 8);
                        mma_bf16(acc3[nb], a0, a1, a2, a3, b0, b1);
                        const __nv_bfloat16* bl = bl_base + nb * 8 * W3_STR + kk;
                        uint32_t c0 = *(const uint32_t*)(bl);
                        uint32_t c1 = *(const uint32_t*)(bl + 8);
                        mma_bf16(acc3[nb], a0, a1, a2, a3, c0, c1);
                    }
                }
            }
            __syncthreads();   // protect w3t/s2 before next chunk's prefetch
        } // chunks
    } // time steps

    // ======== Final output: out = acc/T + b3 ========
    #pragma unroll
    for (int nb = 0; nb < 8; ++nb) {
        int o = wn * 64 + nb * 8 + t * 2;
        float2 bb = *(const float2*)(b3 + o);
        #pragma unroll
        for (int h = 0; h < 2; ++h) {
            int r = row0 + wm * 16 + g + h * 8;
            float2 v;
            v.x = acc3[nb][h * 2 + 0] / (float)T_STEPS + bb.x;
            v.y = acc3[nb][h * 2 + 1] / (float)T_STEPS + bb.y;
            *(float2*)(out + (size_t)r * NOUT + o) = v;
        }
    }
}

// ---------------------------------------------------------------------------
// Launch
// ---------------------------------------------------------------------------
extern "C" void kernel_launch(void* const* d_in, const int* in_sizes, int n_in,
                              void* d_out, int out_size) {
    (void)in_sizes; (void)n_in; (void)out_size;
    const float* x  = (const float*)d_in[0];
    const float* W1 = (const float*)d_in[1];
    const float* b1 = (const float*)d_in[2];
    const float* W2 = (const float*)d_in[3];
    const float* b2 = (const float*)d_in[4];
    const float* W3 = (const float*)d_in[5];
    const float* b3 = (const float*)d_in[6];
    float* out = (float*)d_out;

    const int nconv = HID * HID + NOUT * HID;
    prep_kernel<<<(nconv + 255) / 256, 256>>>(W2, W3);

    dim3 zgrid(HID / 64, BATCH / 64);
    z1_kernel<<<zgrid, 256>>>(x, W1, b1);

    cudaFuncSetAttribute(snn_kernel, cudaFuncAttributeMaxDynamicSharedMemorySize, SMEM_TOTAL);
    snn_kernel<<<BATCH / 64, 256, SMEM_TOTAL>>>(b2, b3, out);
}

// round 5
// speedup vs baseline: 1.1589x; 1.1540x over previous
#include <cuda_runtime.h>
#include <cuda_bf16.h>
#include <cstdint>

#define BETA_F   0.9355f
#define T_STEPS  100
#define BATCH    8192
#define NIN      512
#define HID      512
#define NOUT     128

// ---------------------------------------------------------------------------
// Persistent device state
// ---------------------------------------------------------------------------
__device__ alignas(128) __nv_bfloat16 g_W2hi[HID * HID];
__device__ alignas(128) __nv_bfloat16 g_W2lo[HID * HID];
__device__ alignas(128) __nv_bfloat16 g_W3hi[NOUT * HID];
__device__ alignas(128) __nv_bfloat16 g_W3lo[NOUT * HID];
__device__ alignas(128) float g_z1[BATCH * HID];
__device__ alignas(128) float g_m1[BATCH * HID];
__device__ alignas(128) float g_m2[BATCH * HID];

// ---------------------------------------------------------------------------
// SMEM map (bytes):
//   s1   : [64 rows][512 bf16], stride 520 el (1040 B, 65x16B odd)  @ 0       66560
//   ring : 2 buffers x (hi 128x136-stride + lo)  = 2 x 69632        @ 66560   139264
//          (tile = [128 n][128 k] bf16, stride 136 el = 272 B, 17x16B odd;
//           hi at +0, lo at +34816)
//   s2   : [64 rows][128 bf16], stride 136 el (272 B)               @ 205824  17408
//   total 223232  (< 227 KB limit)
// ---------------------------------------------------------------------------
#define S1_OFF   0
#define S1B      1040          // s1 row stride bytes
#define WB_OFF   66560
#define WBB      272           // ring/s2 row stride bytes
#define TILE_HI  34816         // 128 * 272
#define TILE_SZ  69632         // hi + lo
#define S2_OFF   205824
#define SMEM_TOTAL 223232

// ---------------------------------------------------------------------------
// PTX helpers
// ---------------------------------------------------------------------------
__device__ __forceinline__ uint32_t smem_u32(const void* p) {
    uint32_t a;
    asm("{ .reg .u64 t; cvta.to.shared.u64 t, %1; cvt.u32.u64 %0, t; }" : "=r"(a) : "l"(p));
    return a;
}
__device__ __forceinline__ void cp_async16(void* dst, const void* src) {
    uint32_t s = (uint32_t)__cvta_generic_to_shared(dst);
    asm volatile("cp.async.cg.shared.global [%0], [%1], 16;\n" :: "r"(s), "l"(src) : "memory");
}
__device__ __forceinline__ void cp_commit() {
    asm volatile("cp.async.commit_group;\n" ::: "memory");
}
template <int N>
__device__ __forceinline__ void cp_wait() {
    asm volatile("cp.async.wait_group %0;\n" :: "n"(N) : "memory");
}
__device__ __forceinline__ void ldsm4(uint32_t* r, uint32_t a) {
    asm volatile("ldmatrix.sync.aligned.m8n8.x4.shared.b16 {%0,%1,%2,%3}, [%4];"
                 : "=r"(r[0]), "=r"(r[1]), "=r"(r[2]), "=r"(r[3]) : "r"(a));
}
__device__ __forceinline__ void mma_bf16(float* c,
                                         uint32_t a0, uint32_t a1, uint32_t a2, uint32_t a3,
                                         uint32_t b0, uint32_t b1) {
    asm volatile(
        "mma.sync.aligned.m16n8k16.row.col.f32.bf16.bf16.f32 "
        "{%0,%1,%2,%3}, {%4,%5,%6,%7}, {%8,%9}, {%0,%1,%2,%3};\n"
        : "+f"(c[0]), "+f"(c[1]), "+f"(c[2]), "+f"(c[3])
        : "r"(a0), "r"(a1), "r"(a2), "r"(a3), "r"(b0), "r"(b1));
}

// 64x128 += A(64 x 128, ASTRB row stride) @ B(128 x 128, hi+lo at +TILE_HI)^T
// Warp layout: wm in {0,1} -> 32 M-rows, wn in {0..3} -> 32 N-cols.
// acc[2][4][4]: [mb 16-row block][n8 block][mma c-frag]
template <int ASTRB>
__device__ __forceinline__ void mma_k128(float acc[2][4][4], uint32_t aBase, uint32_t bBase) {
    #pragma unroll
    for (int kk = 0; kk < 8; ++kk) {
        uint32_t A0[4], A1[4];
        ldsm4(A0, aBase + kk * 32);
        ldsm4(A1, aBase + 16 * ASTRB + kk * 32);
        #pragma unroll
        for (int p = 0; p < 2; ++p) {
            uint32_t BH[4], BL[4];
            uint32_t bb = bBase + p * (16 * WBB) + kk * 32;
            ldsm4(BH, bb);
            ldsm4(BL, bb + TILE_HI);
            mma_bf16(acc[0][2 * p],     A0[0], A0[1], A0[2], A0[3], BH[0], BH[1]);
            mma_bf16(acc[0][2 * p + 1], A0[0], A0[1], A0[2], A0[3], BH[2], BH[3]);
            mma_bf16(acc[1][2 * p],     A1[0], A1[1], A1[2], A1[3], BH[0], BH[1]);
            mma_bf16(acc[1][2 * p + 1], A1[0], A1[1], A1[2], A1[3], BH[2], BH[3]);
            mma_bf16(acc[0][2 * p],     A0[0], A0[1], A0[2], A0[3], BL[0], BL[1]);
            mma_bf16(acc[0][2 * p + 1], A0[0], A0[1], A0[2], A0[3], BL[2], BL[3]);
            mma_bf16(acc[1][2 * p],     A1[0], A1[1], A1[2], A1[3], BL[0], BL[1]);
            mma_bf16(acc[1][2 * p + 1], A1[0], A1[1], A1[2], A1[3], BL[2], BL[3]);
        }
    }
}

// ---------------------------------------------------------------------------
// Kernel 1: exact bf16 hi+lo split of W2/W3
// ---------------------------------------------------------------------------
__global__ void prep_kernel(const float* __restrict__ W2, const float* __restrict__ W3) {
    int i = blockIdx.x * blockDim.x + threadIdx.x;
    const int n2 = HID * HID;
    const int n3 = NOUT * HID;
    if (i < n2) {
        float w = W2[i];
        __nv_bfloat16 h = __float2bfloat16(w);
        g_W2hi[i] = h;
        g_W2lo[i] = __float2bfloat16(w - __bfloat162float(h));
    } else if (i < n2 + n3) {
        int j = i - n2;
        float w = W3[j];
        __nv_bfloat16 h = __float2bfloat16(w);
        g_W3hi[j] = h;
        g_W3lo[j] = __float2bfloat16(w - __bfloat162float(h));
    }
}

// ---------------------------------------------------------------------------
// Kernel 2: z1 = x @ W1^T + b1 (fp32 SIMT, one-time)
// ---------------------------------------------------------------------------
__global__ void __launch_bounds__(256) z1_kernel(const float* __restrict__ x,
                                                 const float* __restrict__ W1,
                                                 const float* __restrict__ b1) {
    __shared__ float Xs[16][68];
    __shared__ float Ws[16][68];
    const int tid = threadIdx.x;
    const int bm = blockIdx.y * 64;
    const int bn = blockIdx.x * 64;
    const int tx = tid & 15, ty = tid >> 4;
    const int lrow = tid >> 2;
    const int lk = (tid & 3) * 4;

    float c[4][4] = {};
    for (int k0 = 0; k0 < NIN; k0 += 16) {
        float4 xa = *(const float4*)(x  + (size_t)(bm + lrow) * NIN + k0 + lk);
        float4 wa = *(const float4*)(W1 + (size_t)(bn + lrow) * NIN + k0 + lk);
        __syncthreads();
        Xs[lk + 0][lrow] = xa.x; Xs[lk + 1][lrow] = xa.y;
        Xs[lk + 2][lrow] = xa.z; Xs[lk + 3][lrow] = xa.w;
        Ws[lk + 0][lrow] = wa.x; Ws[lk + 1][lrow] = wa.y;
        Ws[lk + 2][lrow] = wa.z; Ws[lk + 3][lrow] = wa.w;
        __syncthreads();
        #pragma unroll
        for (int k = 0; k < 16; ++k) {
            float a[4], b[4];
            #pragma unroll
            for (int i = 0; i < 4; ++i) a[i] = Xs[k][ty * 4 + i];
            #pragma unroll
            for (int j = 0; j < 4; ++j) b[j] = Ws[k][tx * 4 + j];
            #pragma unroll
            for (int i = 0; i < 4; ++i)
                #pragma unroll
                for (int j = 0; j < 4; ++j)
                    c[i][j] += a[i] * b[j];
        }
    }
    #pragma unroll
    for (int i = 0; i < 4; ++i)
        #pragma unroll
        for (int j = 0; j < 4; ++j)
            g_z1[(size_t)(bm + ty * 4 + i) * HID + bn + tx * 4 + j] = c[i][j] + b1[bn + tx * 4 + j];
}

// ---------------------------------------------------------------------------
// Ring tile loader. Tile j in [0,20): c = j/5 (chunk), r = j%5.
//   r<4 : W2 tile [128 n][128 k], n = chunk cols, k-window r
//   r==4: W3 tile [128 o][128 k], k-window = chunk c
// ---------------------------------------------------------------------------
__device__ __forceinline__ void load_tile(int j, int buf, int tid, char* sm) {
    const int c = j / 5, r = j - c * 5;
    char* dst = sm + WB_OFF + buf * TILE_SZ;
    #pragma unroll
    for (int q = 0; q < 8; ++q) {
        int lin = q * 256 + tid;            // 0..2047
        int n = lin >> 4;                   // 0..127
        int k8 = (lin & 15) * 8;            // 0..120 (elements)
        char* d = dst + n * WBB + k8 * 2;
        if (r < 4) {
            size_t off = (size_t)(c * 128 + n) * HID + r * 128 + k8;
            cp_async16(d, g_W2hi + off);
            cp_async16(d + TILE_HI, g_W2lo + off);
        } else {
            size_t off = (size_t)n * HID + c * 128 + k8;
            cp_async16(d, g_W3hi + off);
            cp_async16(d + TILE_HI, g_W3lo + off);
        }
    }
    cp_commit();
}

// ---------------------------------------------------------------------------
// Kernel 3: persistent fused SNN (mma.sync + ldmatrix).
// 128 CTAs x 256 threads, 64 batch rows per CTA, all 100 steps in-kernel.
// ---------------------------------------------------------------------------
__global__ void __launch_bounds__(256, 1) snn_kernel(const float* __restrict__ b2g,
                                                     const float* __restrict__ b3g,
                                                     float* __restrict__ outp) {
    extern __shared__ char sm[];
    const uint32_t smb = smem_u32(sm);
    const int tid  = threadIdx.x;
    const int warp = tid >> 5;
    const int lane = tid & 31;
    const int wm   = warp >> 2;        // 0..1 : 32-row M block
    const int wn   = warp & 3;         // 0..3 : 32-col N block
    const int row0 = blockIdx.x * 64;

    // ldmatrix per-lane offsets
    const int rowl_a = (lane & 7) + ((lane >> 3) & 1) * 8;   // A: lanes 8-15 -> +8 rows
    const int kl_a   = ((lane >> 4) & 1) * 8;                // A: lanes 16+  -> +8 k
    const int rowl_b = (lane & 7) + ((lane >> 4) & 1) * 8;   // B: lanes 16+  -> +8 rows
    const int kl_b   = ((lane >> 3) & 1) * 8;                // B: lanes 8-15 -> +8 k

    const uint32_t aS1 = smb + S1_OFF + (uint32_t)(wm * 32 + rowl_a) * S1B + kl_a * 2;
    const uint32_t aS2 = smb + S2_OFF + (uint32_t)(wm * 32 + rowl_a) * WBB + kl_a * 2;
    const uint32_t bOff = (uint32_t)(wn * 32 + rowl_b) * WBB + kl_b * 2;

    // ---- zero membranes for this tile ----
    const float4 z4 = make_float4(0.f, 0.f, 0.f, 0.f);
    #pragma unroll
    for (int q = 0; q < 32; ++q) {
        size_t gi = (size_t)row0 * HID + (size_t)(q * 256 + tid) * 4;
        *(float4*)(g_m1 + gi) = z4;
        *(float4*)(g_m2 + gi) = z4;
    }
    __syncthreads();

    load_tile(0, 0, tid, sm);

    float acc3[2][4][4] = {};     // persistent GEMM3 accumulator
    float accz[2][4][4] = {};     // per-chunk GEMM2 accumulator

    #pragma unroll 1
    for (int step = 0; step < T_STEPS; ++step) {
        // ======== LIF layer 1 -> s1 (bf16 {0,1}) ========
        #pragma unroll 4
        for (int i = 0; i < 32; ++i) {
            int l = i * 256 + tid;                 // float4 index 0..8191
            size_t gi = (size_t)row0 * HID + (size_t)l * 4;
            float4 z = *(const float4*)(g_z1 + gi);
            float4 m = *(float4*)(g_m1 + gi);
            unsigned short sx, sy, sz, sw;
            m.x = BETA_F * m.x + z.x; if (m.x >= 1.0f) { m.x -= 1.0f; sx = 0x3F80; } else sx = 0;
            m.y = BETA_F * m.y + z.y; if (m.y >= 1.0f) { m.y -= 1.0f; sy = 0x3F80; } else sy = 0;
            m.z = BETA_F * m.z + z.z; if (m.z >= 1.0f) { m.z -= 1.0f; sz = 0x3F80; } else sz = 0;
            m.w = BETA_F * m.w + z.w; if (m.w >= 1.0f) { m.w -= 1.0f; sw = 0x3F80; } else sw = 0;
            *(float4*)(g_m1 + gi) = m;
            int lr = (l * 4) >> 9;                 // local row
            int lc = (l * 4) & 511;                // local col (multiple of 4)
            *(uint2*)(sm + S1_OFF + lr * S1B + lc * 2) =
                make_uint2((uint32_t)sx | ((uint32_t)sy << 16),
                           (uint32_t)sz | ((uint32_t)sw << 16));
        }
        // visibility of s1 guaranteed by the sync at top of tile 0 below

        // ======== 20 ring tiles: per chunk 4x GEMM2, epilogue, 1x GEMM3 ========
        #pragma unroll 1
        for (int t = 0; t < 20; ++t) {
            const int c = t / 5, r = t - c * 5;
            const int gt = step * 20 + t;
            const uint32_t ringb = smb + WB_OFF + (uint32_t)(gt & 1) * TILE_SZ;

            cp_wait<0>();
            __syncthreads();             // tile gt resident+visible; prev buffer free
            if (gt + 1 < T_STEPS * 20) load_tile((t + 1) % 20, (gt + 1) & 1, tid, sm);

            if (r < 4) {
                // GEMM2: accz += s1[:, r*128 +: 128] @ W2tile^T (hi+lo)
                mma_k128<S1B>(accz, aS1 + (uint32_t)(r * 128) * 2, ringb + bOff);
            } else {
                // ---- epilogue: z2 = accz + b2 -> LIF2 -> s2 ----
                const int rbase = wm * 32 + (lane >> 2);
                const int cloc0 = wn * 32 + (lane & 3) * 2;
                #pragma unroll
                for (int nb = 0; nb < 4; ++nb) {
                    const int cloc = cloc0 + nb * 8;
                    const int col  = c * 128 + cloc;
                    const float2 bb = *(const float2*)(b2g + col);
                    #pragma unroll
                    for (int mb = 0; mb < 2; ++mb)
                    #pragma unroll
                    for (int h = 0; h < 2; ++h) {
                        const int row = rbase + mb * 16 + h * 8;
                        float* m2p = g_m2 + (size_t)(row0 + row) * HID + col;
                        float2 m = *(float2*)m2p;
                        m.x = BETA_F * m.x + (accz[mb][nb][h * 2 + 0] + bb.x);
                        m.y = BETA_F * m.y + (accz[mb][nb][h * 2 + 1] + bb.y);
                        uint32_t s0, s1v;
                        if (m.x >= 1.0f) { m.x -= 1.0f; s0 = 0x3F80u; } else s0 = 0;
                        if (m.y >= 1.0f) { m.y -= 1.0f; s1v = 0x3F80u; } else s1v = 0;
                        *(float2*)m2p = m;
                        *(uint32_t*)(sm + S2_OFF + row * WBB + cloc * 2) = s0 | (s1v << 16);
                    }
                }
                __syncthreads();         // s2 visible to all warps

                // GEMM3: acc3 += s2 @ W3tile^T (hi+lo)
                mma_k128<WBB>(acc3, aS2, ringb + bOff);

                // reset accz for next chunk
                #pragma unroll
                for (int mb = 0; mb < 2; ++mb)
                    #pragma unroll
                    for (int nb = 0; nb < 4; ++nb)
                        #pragma unroll
                        for (int e = 0; e < 4; ++e)
                            accz[mb][nb][e] = 0.f;
            }
        }
    }

    // ======== Final output: out = acc3/T + b3 ========
    const float inv = 1.0f / (float)T_STEPS;
    const int rbase = wm * 32 + (lane >> 2);
    const int cb = wn * 32 + (lane & 3) * 2;
    #pragma unroll
    for (int nb = 0; nb < 4; ++nb) {
        const int col = cb + nb * 8;
        const float2 bb = *(const float2*)(b3g + col);
        #pragma unroll
        for (int mb = 0; mb < 2; ++mb)
        #pragma unroll
        for (int h = 0; h < 2; ++h) {
            const int row = row0 + rbase + mb * 16 + h * 8;
            float2 v;
            v.x = acc3[mb][nb][h * 2 + 0] * inv + bb.x;
            v.y = acc3[mb][nb][h * 2 + 1] * inv + bb.y;
            *(float2*)(outp + (size_t)row * NOUT + col) = v;
        }
    }
}

// ---------------------------------------------------------------------------
// Launch
// ---------------------------------------------------------------------------
extern "C" void kernel_launch(void* const* d_in, const int* in_sizes, int n_in,
                              void* d_out, int out_size) {
    (void)in_sizes; (void)n_in; (void)out_size;
    const float* x  = (const float*)d_in[0];
    const float* W1 = (const float*)d_in[1];
    const float* b1 = (const float*)d_in[2];
    const float* W2 = (const float*)d_in[3];
    const float* b2 = (const float*)d_in[4];
    const float* W3 = (const float*)d_in[5];
    const float* b3 = (const float*)d_in[6];
    float* out = (float*)d_out;

    const int nconv = HID * HID + NOUT * HID;
    prep_kernel<<<(nconv + 255) / 256, 256>>>(W2, W3);

    dim3 zgrid(HID / 64, BATCH / 64);
    z1_kernel<<<zgrid, 256>>>(x, W1, b1);

    cudaFuncSetAttribute(snn_kernel, cudaFuncAttributeMaxDynamicSharedMemorySize, SMEM_TOTAL);
    snn_kernel<<<BATCH / 64, 256, SMEM_TOTAL>>>(b2, b3, out);
}

// round 7
// speedup vs baseline: 1.3071x; 1.1279x over previous
#include <cuda_runtime.h>
#include <cuda_bf16.h>
#include <cstdint>

#define BETA_F   0.9355f
#define T_STEPS  100
#define BATCH    8192
#define NIN      512
#define HID      512
#define NOUT     128
#define THREADS  512

// ---------------------------------------------------------------------------
// Persistent device state
// ---------------------------------------------------------------------------
__device__ alignas(128) __nv_bfloat16 g_W2hi[HID * HID];
__device__ alignas(128) __nv_bfloat16 g_W2lo[HID * HID];
__device__ alignas(128) __nv_bfloat16 g_W3hi[NOUT * HID];
__device__ alignas(128) __nv_bfloat16 g_W3lo[NOUT * HID];
__device__ alignas(128) float g_z1[BATCH * HID];
__device__ alignas(128) float g_m1[BATCH * HID];
__device__ alignas(128) float g_m2[BATCH * HID];

// ---------------------------------------------------------------------------
// SMEM map (bytes):
//   s1   : [64 rows][512 bf16], stride 520 el (1040 B)              @ 0       66560
//   ring : 2 buffers x (hi 128x136-stride + lo) = 2 x 69632         @ 66560   139264
//   s2   : [64 rows][128 bf16], stride 136 el (272 B)               @ 205824  17408
//   total 223232
// ---------------------------------------------------------------------------
#define S1_OFF   0
#define S1B      1040
#define WB_OFF   66560
#define WBB      272
#define TILE_HI  34816
#define TILE_SZ  69632
#define S2_OFF   205824
#define SMEM_TOTAL 223232

// ---------------------------------------------------------------------------
// PTX helpers
// ---------------------------------------------------------------------------
__device__ __forceinline__ uint32_t smem_u32(const void* p) {
    uint32_t a;
    asm("{ .reg .u64 t; cvta.to.shared.u64 t, %1; cvt.u32.u64 %0, t; }" : "=r"(a) : "l"(p));
    return a;
}
__device__ __forceinline__ void cp_async16(void* dst, const void* src) {
    uint32_t s = (uint32_t)__cvta_generic_to_shared(dst);
    asm volatile("cp.async.cg.shared.global [%0], [%1], 16;\n" :: "r"(s), "l"(src) : "memory");
}
__device__ __forceinline__ void cp_commit() {
    asm volatile("cp.async.commit_group;\n" ::: "memory");
}
template <int N>
__device__ __forceinline__ void cp_wait() {
    asm volatile("cp.async.wait_group %0;\n" :: "n"(N) : "memory");
}
__device__ __forceinline__ void ldsm4(uint32_t* r, uint32_t a) {
    asm volatile("ldmatrix.sync.aligned.m8n8.x4.shared.b16 {%0,%1,%2,%3}, [%4];"
                 : "=r"(r[0]), "=r"(r[1]), "=r"(r[2]), "=r"(r[3]) : "r"(a));
}
__device__ __forceinline__ void mma_bf16(float* c,
                                         uint32_t a0, uint32_t a1, uint32_t a2, uint32_t a3,
                                         uint32_t b0, uint32_t b1) {
    asm volatile(
        "mma.sync.aligned.m16n8k16.row.col.f32.bf16.bf16.f32 "
        "{%0,%1,%2,%3}, {%4,%5,%6,%7}, {%8,%9}, {%0,%1,%2,%3};\n"
        : "+f"(c[0]), "+f"(c[1]), "+f"(c[2]), "+f"(c[3])
        : "r"(a0), "r"(a1), "r"(a2), "r"(a3), "r"(b0), "r"(b1));
}

// 32x16 warp tile: acc[2 m16][2 n8][4] += A(32 x 128) @ B(hi+lo)^T
// Wave-ordered: 4 hi-MMAs then 4 lo-MMAs per kk (RAW distance 4, hidden by
// 4 warps/SMSP).
template <int ASTRB>
__device__ __forceinline__ void mma_k128(float acc[2][2][4], uint32_t aBase, uint32_t bBase) {
    #pragma unroll
    for (int kk = 0; kk < 8; ++kk) {
        uint32_t A0[4], A1[4], BH[4], BL[4];
        ldsm4(A0, aBase + kk * 32);
        ldsm4(A1, aBase + 16 * ASTRB + kk * 32);
        ldsm4(BH, bBase + kk * 32);
        ldsm4(BL, bBase + TILE_HI + kk * 32);
        mma_bf16(acc[0][0], A0[0], A0[1], A0[2], A0[3], BH[0], BH[1]);
        mma_bf16(acc[0][1], A0[0], A0[1], A0[2], A0[3], BH[2], BH[3]);
        mma_bf16(acc[1][0], A1[0], A1[1], A1[2], A1[3], BH[0], BH[1]);
        mma_bf16(acc[1][1], A1[0], A1[1], A1[2], A1[3], BH[2], BH[3]);
        mma_bf16(acc[0][0], A0[0], A0[1], A0[2], A0[3], BL[0], BL[1]);
        mma_bf16(acc[0][1], A0[0], A0[1], A0[2], A0[3], BL[2], BL[3]);
        mma_bf16(acc[1][0], A1[0], A1[1], A1[2], A1[3], BL[0], BL[1]);
        mma_bf16(acc[1][1], A1[0], A1[1], A1[2], A1[3], BL[2], BL[3]);
    }
}

// ---------------------------------------------------------------------------
// Kernel 1: exact bf16 hi+lo split of W2/W3
// ---------------------------------------------------------------------------
__global__ void prep_kernel(const float* __restrict__ W2, const float* __restrict__ W3) {
    int i = blockIdx.x * blockDim.x + threadIdx.x;
    const int n2 = HID * HID;
    const int n3 = NOUT * HID;
    if (i < n2) {
        float w = W2[i];
        __nv_bfloat16 h = __float2bfloat16(w);
        g_W2hi[i] = h;
        g_W2lo[i] = __float2bfloat16(w - __bfloat162float(h));
    } else if (i < n2 + n3) {
        int j = i - n2;
        float w = W3[j];
        __nv_bfloat16 h = __float2bfloat16(w);
        g_W3hi[j] = h;
        g_W3lo[j] = __float2bfloat16(w - __bfloat162float(h));
    }
}

// ---------------------------------------------------------------------------
// Kernel 2: z1 = x @ W1^T + b1 (fp32 SIMT, one-time)
// ---------------------------------------------------------------------------
__global__ void __launch_bounds__(256) z1_kernel(const float* __restrict__ x,
                                                 const float* __restrict__ W1,
                                                 const float* __restrict__ b1) {
    __shared__ float Xs[16][68];
    __shared__ float Ws[16][68];
    const int tid = threadIdx.x;
    const int bm = blockIdx.y * 64;
    const int bn = blockIdx.x * 64;
    const int tx = tid & 15, ty = tid >> 4;
    const int lrow = tid >> 2;
    const int lk = (tid & 3) * 4;

    float c[4][4] = {};
    for (int k0 = 0; k0 < NIN; k0 += 16) {
        float4 xa = *(const float4*)(x  + (size_t)(bm + lrow) * NIN + k0 + lk);
        float4 wa = *(const float4*)(W1 + (size_t)(bn + lrow) * NIN + k0 + lk);
        __syncthreads();
        Xs[lk + 0][lrow] = xa.x; Xs[lk + 1][lrow] = xa.y;
        Xs[lk + 2][lrow] = xa.z; Xs[lk + 3][lrow] = xa.w;
        Ws[lk + 0][lrow] = wa.x; Ws[lk + 1][lrow] = wa.y;
        Ws[lk + 2][lrow] = wa.z; Ws[lk + 3][lrow] = wa.w;
        __syncthreads();
        #pragma unroll
        for (int k = 0; k < 16; ++k) {
            float a[4], b[4];
            #pragma unroll
            for (int i = 0; i < 4; ++i) a[i] = Xs[k][ty * 4 + i];
            #pragma unroll
            for (int j = 0; j < 4; ++j) b[j] = Ws[k][tx * 4 + j];
            #pragma unroll
            for (int i = 0; i < 4; ++i)
                #pragma unroll
                for (int j = 0; j < 4; ++j)
                    c[i][j] += a[i] * b[j];
        }
    }
    #pragma unroll
    for (int i = 0; i < 4; ++i)
        #pragma unroll
        for (int j = 0; j < 4; ++j)
            g_z1[(size_t)(bm + ty * 4 + i) * HID + bn + tx * 4 + j] = c[i][j] + b1[bn + tx * 4 + j];
}

// ---------------------------------------------------------------------------
// Ring tile loader. Tile j in [0,20): c = j/5, r = j%5.
//   r<4 : W2 tile [128 n][128 k]; r==4: W3 tile [128 o][128 k]
// ---------------------------------------------------------------------------
__device__ __forceinline__ void load_tile(int j, int buf, int tid, char* sm) {
    const int c = j / 5, r = j - c * 5;
    char* dst = sm + WB_OFF + buf * TILE_SZ;
    #pragma unroll
    for (int q = 0; q < 4; ++q) {
        int lin = q * THREADS + tid;        // 0..2047
        int n = lin >> 4;
        int k8 = (lin & 15) * 8;
        char* d = dst + n * WBB + k8 * 2;
        if (r < 4) {
            size_t off = (size_t)(c * 128 + n) * HID + r * 128 + k8;
            cp_async16(d, g_W2hi + off);
            cp_async16(d + TILE_HI, g_W2lo + off);
        } else {
            size_t off = (size_t)n * HID + c * 128 + k8;
            cp_async16(d, g_W3hi + off);
            cp_async16(d + TILE_HI, g_W3lo + off);
        }
    }
    cp_commit();
}

// ---------------------------------------------------------------------------
// Kernel 3: persistent fused SNN. 128 CTAs x 512 threads (16 warps),
// 64 batch rows per CTA, all 100 steps in-kernel.
// Warp grid: wm in {0,1} (32 M-rows), wn in {0..7} (16 N-cols).
// ---------------------------------------------------------------------------
__global__ void __launch_bounds__(THREADS, 1) snn_kernel(const float* __restrict__ b2g,
                                                         const float* __restrict__ b3g,
                                                         float* __restrict__ outp) {
    extern __shared__ char sm[];
    const uint32_t smb = smem_u32(sm);
    const int tid  = threadIdx.x;
    const int warp = tid >> 5;
    const int lane = tid & 31;
    const int wm   = warp >> 3;        // 0..1
    const int wn   = warp & 7;         // 0..7
    const int row0 = blockIdx.x * 64;

    const int rowl_a = (lane & 7) + ((lane >> 3) & 1) * 8;
    const int kl_a   = ((lane >> 4) & 1) * 8;
    const int rowl_b = (lane & 7) + ((lane >> 4) & 1) * 8;
    const int kl_b   = ((lane >> 3) & 1) * 8;

    const uint32_t aS1 = smb + S1_OFF + (uint32_t)(wm * 32 + rowl_a) * S1B + kl_a * 2;
    const uint32_t aS2 = smb + S2_OFF + (uint32_t)(wm * 32 + rowl_a) * WBB + kl_a * 2;
    const uint32_t bOff = (uint32_t)(wn * 16 + rowl_b) * WBB + kl_b * 2;

    // ---- zero membranes for this tile ----
    const float4 z4 = make_float4(0.f, 0.f, 0.f, 0.f);
    #pragma unroll
    for (int q = 0; q < 16; ++q) {
        size_t gi = (size_t)row0 * HID + (size_t)(q * THREADS + tid) * 4;
        *(float4*)(g_m1 + gi) = z4;
        *(float4*)(g_m2 + gi) = z4;
    }
    __syncthreads();

    load_tile(0, 0, tid, sm);

    float acc3[2][2][4] = {};     // persistent GEMM3 accumulator
    float accz[2][2][4] = {};     // per-chunk GEMM2 accumulator

    #pragma unroll 1
    for (int step = 0; step < T_STEPS; ++step) {
        // ======== LIF layer 1 -> s1 (bf16 {0,1}) ========
        #pragma unroll 4
        for (int i = 0; i < 16; ++i) {
            int l = i * THREADS + tid;             // float4 index 0..8191
            size_t gi = (size_t)row0 * HID + (size_t)l * 4;
            float4 z = *(const float4*)(g_z1 + gi);
            float4 m = *(float4*)(g_m1 + gi);
            unsigned short sx, sy, sz, sw;
            m.x = BETA_F * m.x + z.x; if (m.x >= 1.0f) { m.x -= 1.0f; sx = 0x3F80; } else sx = 0;
            m.y = BETA_F * m.y + z.y; if (m.y >= 1.0f) { m.y -= 1.0f; sy = 0x3F80; } else sy = 0;
            m.z = BETA_F * m.z + z.z; if (m.z >= 1.0f) { m.z -= 1.0f; sz = 0x3F80; } else sz = 0;
            m.w = BETA_F * m.w + z.w; if (m.w >= 1.0f) { m.w -= 1.0f; sw = 0x3F80; } else sw = 0;
            *(float4*)(g_m1 + gi) = m;
            int lr = (l * 4) >> 9;
            int lc = (l * 4) & 511;
            *(uint2*)(sm + S1_OFF + lr * S1B + lc * 2) =
                make_uint2((uint32_t)sx | ((uint32_t)sy << 16),
                           (uint32_t)sz | ((uint32_t)sw << 16));
        }

        // ======== 20 ring tiles: per chunk 4x GEMM2, epilogue, 1x GEMM3 ========
        #pragma unroll 1
        for (int t = 0; t < 20; ++t) {
            const int c = t / 5, r = t - c * 5;
            const int gt = step * 20 + t;
            const uint32_t ringb = smb + WB_OFF + (uint32_t)(gt & 1) * TILE_SZ;

            cp_wait<0>();
            __syncthreads();             // tile gt resident; prev buffer free; s1/s2 visible
            if (gt + 1 < T_STEPS * 20) load_tile((t + 1) % 20, (gt + 1) & 1, tid, sm);

            if (r < 4) {
                mma_k128<S1B>(accz, aS1 + (uint32_t)(r * 128) * 2, ringb + bOff);
            } else {
                // ---- epilogue: z2 = accz + b2 -> LIF2 -> s2 ----
                const int rbase = wm * 32 + (lane >> 2);
                const int cloc0 = wn * 16 + (lane & 3) * 2;
                #pragma unroll
                for (int nb = 0; nb < 2; ++nb) {
                    const int cloc = cloc0 + nb * 8;
                    const int col  = c * 128 + cloc;
                    const float2 bb = *(const float2*)(b2g + col);
                    #pragma unroll
                    for (int mb = 0; mb < 2; ++mb)
                    #pragma unroll
                    for (int h = 0; h < 2; ++h) {
                        const int row = rbase + mb * 16 + h * 8;
                        float* m2p = g_m2 + (size_t)(row0 + row) * HID + col;
                        float2 m = *(float2*)m2p;
                        m.x = BETA_F * m.x + (accz[mb][nb][h * 2 + 0] + bb.x);
                        m.y = BETA_F * m.y + (accz[mb][nb][h * 2 + 1] + bb.y);
                        uint32_t s0, s1v;
                        if (m.x >= 1.0f) { m.x -= 1.0f; s0 = 0x3F80u; } else s0 = 0;
                        if (m.y >= 1.0f) { m.y -= 1.0f; s1v = 0x3F80u; } else s1v = 0;
                        *(float2*)m2p = m;
                        *(uint32_t*)(sm + S2_OFF + row * WBB + cloc * 2) = s0 | (s1v << 16);
                        accz[mb][nb][h * 2 + 0] = 0.f;
                        accz[mb][nb][h * 2 + 1] = 0.f;
                    }
                }
                __syncthreads();         // s2 visible to all warps

                mma_k128<WBB>(acc3, aS2, ringb + bOff);
            }
        }
    }

    // ======== Final output: out = acc3/T + b3 ========
    const float inv = 1.0f / (float)T_STEPS;
    const int rbase = wm * 32 + (lane >> 2);
    const int cb = wn * 16 + (lane & 3) * 2;
    #pragma unroll
    for (int nb = 0; nb < 2; ++nb) {
        const int col = cb + nb * 8;
        const float2 bb = *(const float2*)(b3g + col);
        #pragma unroll
        for (int mb = 0; mb < 2; ++mb)
        #pragma unroll
        for (int h = 0; h < 2; ++h) {
            const int row = row0 + rbase + mb * 16 + h * 8;
            float2 v;
            v.x = acc3[mb][nb][h * 2 + 0] * inv + bb.x;
            v.y = acc3[mb][nb][h * 2 + 1] * inv + bb.y;
            *(float2*)(outp + (size_t)row * NOUT + col) = v;
        }
    }
}

// ---------------------------------------------------------------------------
// Launch
// ---------------------------------------------------------------------------
extern "C" void kernel_launch(void* const* d_in, const int* in_sizes, int n_in,
                              void* d_out, int out_size) {
    (void)in_sizes; (void)n_in; (void)out_size;
    const float* x  = (const float*)d_in[0];
    const float* W1 = (const float*)d_in[1];
    const float* b1 = (const float*)d_in[2];
    const float* W2 = (const float*)d_in[3];
    const float* b2 = (const float*)d_in[4];
    const float* W3 = (const float*)d_in[5];
    const float* b3 = (const float*)d_in[6];
    float* out = (float*)d_out;

    const int nconv = HID * HID + NOUT * HID;
    prep_kernel<<<(nconv + 255) / 256, 256>>>(W2, W3);

    dim3 zgrid(HID / 64, BATCH / 64);
    z1_kernel<<<zgrid, 256>>>(x, W1, b1);

    cudaFuncSetAttribute(snn_kernel, cudaFuncAttributeMaxDynamicSharedMemorySize, SMEM_TOTAL);
    snn_kernel<<<BATCH / 64, THREADS, SMEM_TOTAL>>>(b2, b3, out);
}

// round 9
// speedup vs baseline: 2.1193x; 1.6213x over previous
#include <cuda_runtime.h>
#include <cuda_bf16.h>
#include <cstdint>

#define BETA_F   0.9355f
#define T_STEPS  100
#define BATCH    8192
#define NIN      512
#define HID      512
#define NOUT     128
#define THREADS  512

// ---------------------------------------------------------------------------
// Persistent device state
// ---------------------------------------------------------------------------
__device__ alignas(128) int8_t g_W2a[HID * HID];
__device__ alignas(128) int8_t g_W2b[HID * HID];
__device__ alignas(128) int8_t g_W3a[NOUT * HID];
__device__ alignas(128) int8_t g_W3b[NOUT * HID];
__device__ alignas(128) float g_z1[BATCH * HID];
__device__ alignas(128) float g_m1[BATCH * HID];
__device__ alignas(128) float g_m2[BATCH * HID];
__device__ unsigned int g_maxbits[2];   // fabs-max bit patterns of W2, W3

// ---------------------------------------------------------------------------
// SMEM map (bytes):
//   s1   : [64 rows][512 int8], stride 528 (33x16, odd)            @ 0        33792
//   ring : 2 bufs x (termA 128x144 + termB 128x144) = 2 x 36864    @ 33792    73728
//   s2   : [64 rows][128 int8], stride 144 (9x16, odd)             @ 107520    9216
//   total 116736
// ---------------------------------------------------------------------------
#define S1_OFF   0
#define S1B      528
#define WB_OFF   33792
#define WBB      144
#define TERM_B   18432
#define TILE_SZ  36864
#define S2_OFF   107520
#define SMEM_TOTAL 116736

// ---------------------------------------------------------------------------
// PTX helpers
// ---------------------------------------------------------------------------
__device__ __forceinline__ uint32_t smem_u32(const void* p) {
    uint32_t a;
    asm("{ .reg .u64 t; cvta.to.shared.u64 t, %1; cvt.u32.u64 %0, t; }" : "=r"(a) : "l"(p));
    return a;
}
__device__ __forceinline__ void cp_async16(void* dst, const void* src) {
    uint32_t s = (uint32_t)__cvta_generic_to_shared(dst);
    asm volatile("cp.async.cg.shared.global [%0], [%1], 16;\n" :: "r"(s), "l"(src) : "memory");
}
__device__ __forceinline__ void cp_commit() {
    asm volatile("cp.async.commit_group;\n" ::: "memory");
}
template <int N>
__device__ __forceinline__ void cp_wait() {
    asm volatile("cp.async.wait_group %0;\n" :: "n"(N) : "memory");
}
__device__ __forceinline__ void ldsm4(uint32_t* r, uint32_t a) {
    asm volatile("ldmatrix.sync.aligned.m8n8.x4.shared.b16 {%0,%1,%2,%3}, [%4];"
                 : "=r"(r[0]), "=r"(r[1]), "=r"(r[2]), "=r"(r[3]) : "r"(a));
}
// s8 x s8 -> s32, m16n8k32
__device__ __forceinline__ void mma_s8(int* c,
                                       uint32_t a0, uint32_t a1, uint32_t a2, uint32_t a3,
                                       uint32_t b0, uint32_t b1) {
    asm volatile(
        "mma.sync.aligned.m16n8k32.row.col.s32.s8.s8.s32 "
        "{%0,%1,%2,%3}, {%4,%5,%6,%7}, {%8,%9}, {%0,%1,%2,%3};\n"
        : "+r"(c[0]), "+r"(c[1]), "+r"(c[2]), "+r"(c[3])
        : "r"(a0), "r"(a1), "r"(a2), "r"(a3), "r"(b0), "r"(b1));
}

// 32x16 warp tile (int8, k=128): accA/accB[2 m16][2 n8][4] += A @ {termA,termB}^T
template <int ASTRB>
__device__ __forceinline__ void mma_k128_i8(int accA[2][2][4], int accB[2][2][4],
                                            uint32_t aBase, uint32_t bBase) {
    #pragma unroll
    for (int kk = 0; kk < 4; ++kk) {
        uint32_t A0[4], A1[4], BA[4], BB[4];
        ldsm4(A0, aBase + kk * 32);
        ldsm4(A1, aBase + 16 * ASTRB + kk * 32);
        ldsm4(BA, bBase + kk * 32);
        ldsm4(BB, bBase + TERM_B + kk * 32);
        mma_s8(accA[0][0], A0[0], A0[1], A0[2], A0[3], BA[0], BA[1]);
        mma_s8(accA[0][1], A0[0], A0[1], A0[2], A0[3], BA[2], BA[3]);
        mma_s8(accA[1][0], A1[0], A1[1], A1[2], A1[3], BA[0], BA[1]);
        mma_s8(accA[1][1], A1[0], A1[1], A1[2], A1[3], BA[2], BA[3]);
        mma_s8(accB[0][0], A0[0], A0[1], A0[2], A0[3], BB[0], BB[1]);
        mma_s8(accB[0][1], A0[0], A0[1], A0[2], A0[3], BB[2], BB[3]);
        mma_s8(accB[1][0], A1[0], A1[1], A1[2], A1[3], BB[0], BB[1]);
        mma_s8(accB[1][1], A1[0], A1[1], A1[2], A1[3], BB[2], BB[3]);
    }
}

// ---------------------------------------------------------------------------
// Kernel 0: zero the max accumulators (graph-replay determinism)
// ---------------------------------------------------------------------------
__global__ void zero_kernel() {
    g_maxbits[0] = 0u;
    g_maxbits[1] = 0u;
}

// ---------------------------------------------------------------------------
// Kernel 1: fabs-max of W2 and W3 (bit-pattern max == float max for >=0)
// ---------------------------------------------------------------------------
__global__ void max_kernel(const float* __restrict__ W2, const float* __restrict__ W3) {
    const int n2 = HID * HID, n3 = NOUT * HID;
    const int stride = gridDim.x * blockDim.x;
    unsigned int m2 = 0, m3 = 0;
    for (int i = blockIdx.x * blockDim.x + threadIdx.x; i < n2; i += stride)
        m2 = max(m2, __float_as_uint(fabsf(W2[i])));
    for (int i = blockIdx.x * blockDim.x + threadIdx.x; i < n3; i += stride)
        m3 = max(m3, __float_as_uint(fabsf(W3[i])));
    m2 = __reduce_max_sync(0xFFFFFFFFu, m2);
    m3 = __reduce_max_sync(0xFFFFFFFFu, m3);
    if ((threadIdx.x & 31) == 0) {
        atomicMax(&g_maxbits[0], m2);
        atomicMax(&g_maxbits[1], m3);
    }
}

// ---------------------------------------------------------------------------
// Kernel 2: exact 2-term int8 quantization: w = d1*a + d2*b + eps, |eps|<=d1/508
// ---------------------------------------------------------------------------
__global__ void quant_kernel(const float* __restrict__ W2, const float* __restrict__ W3) {
    int i = blockIdx.x * blockDim.x + threadIdx.x;
    const int n2 = HID * HID, n3 = NOUT * HID;
    if (i < n2) {
        const float d1 = __uint_as_float(g_maxbits[0]) * (1.0f / 127.0f);
        const float d2 = d1 * (1.0f / 254.0f);
        float w = W2[i];
        float a = rintf(w / d1);
        float b = rintf((w - a * d1) / d2);
        g_W2a[i] = (int8_t)(int)a;
        g_W2b[i] = (int8_t)(int)b;
    } else if (i < n2 + n3) {
        int j = i - n2;
        const float d1 = __uint_as_float(g_maxbits[1]) * (1.0f / 127.0f);
        const float d2 = d1 * (1.0f / 254.0f);
        float w = W3[j];
        float a = rintf(w / d1);
        float b = rintf((w - a * d1) / d2);
        g_W3a[j] = (int8_t)(int)a;
        g_W3b[j] = (int8_t)(int)b;
    }
}

// ---------------------------------------------------------------------------
// Kernel 3: z1 = x @ W1^T + b1 (fp32 SIMT, one-time)
// ---------------------------------------------------------------------------
__global__ void __launch_bounds__(256) z1_kernel(const float* __restrict__ x,
                                                 const float* __restrict__ W1,
                                                 const float* __restrict__ b1) {
    __shared__ float Xs[16][68];
    __shared__ float Ws[16][68];
    const int tid = threadIdx.x;
    const int bm = blockIdx.y * 64;
    const int bn = blockIdx.x * 64;
    const int tx = tid & 15, ty = tid >> 4;
    const int lrow = tid >> 2;
    const int lk = (tid & 3) * 4;

    float c[4][4] = {};
    for (int k0 = 0; k0 < NIN; k0 += 16) {
        float4 xa = *(const float4*)(x  + (size_t)(bm + lrow) * NIN + k0 + lk);
        float4 wa = *(const float4*)(W1 + (size_t)(bn + lrow) * NIN + k0 + lk);
        __syncthreads();
        Xs[lk + 0][lrow] = xa.x; Xs[lk + 1][lrow] = xa.y;
        Xs[lk + 2][lrow] = xa.z; Xs[lk + 3][lrow] = xa.w;
        Ws[lk + 0][lrow] = wa.x; Ws[lk + 1][lrow] = wa.y;
        Ws[lk + 2][lrow] = wa.z; Ws[lk + 3][lrow] = wa.w;
        __syncthreads();
        #pragma unroll
        for (int k = 0; k < 16; ++k) {
            float a[4], b[4];
            #pragma unroll
            for (int i = 0; i < 4; ++i) a[i] = Xs[k][ty * 4 + i];
            #pragma unroll
            for (int j = 0; j < 4; ++j) b[j] = Ws[k][tx * 4 + j];
            #pragma unroll
            for (int i = 0; i < 4; ++i)
                #pragma unroll
                for (int j = 0; j < 4; ++j)
                    c[i][j] += a[i] * b[j];
        }
    }
    #pragma unroll
    for (int i = 0; i < 4; ++i)
        #pragma unroll
        for (int j = 0; j < 4; ++j)
            g_z1[(size_t)(bm + ty * 4 + i) * HID + bn + tx * 4 + j] = c[i][j] + b1[bn + tx * 4 + j];
}

// ---------------------------------------------------------------------------
// Ring tile loader (int8). Tile j in [0,20): c = j/5, r = j%5.
//   r<4 : W2 tile [128 n][128 k]; r==4: W3 tile [128 o][128 k]. Terms A+B.
// ---------------------------------------------------------------------------
__device__ __forceinline__ void load_tile(int j, int buf, int tid, char* sm) {
    const int c = j / 5, r = j - c * 5;
    char* dst = sm + WB_OFF + buf * TILE_SZ;
    #pragma unroll
    for (int q = 0; q < 2; ++q) {
        int lin = q * THREADS + tid;        // 0..1023
        int n = lin >> 3;                   // 0..127
        int seg = (lin & 7) * 16;           // byte offset in row
        char* d = dst + n * WBB + seg;
        if (r < 4) {
            size_t off = (size_t)(c * 128 + n) * HID + r * 128 + seg;
            cp_async16(d, g_W2a + off);
            cp_async16(d + TERM_B, g_W2b + off);
        } else {
            size_t off = (size_t)n * HID + c * 128 + seg;
            cp_async16(d, g_W3a + off);
            cp_async16(d + TERM_B, g_W3b + off);
        }
    }
    cp_commit();
}

// ---------------------------------------------------------------------------
// Kernel 4: persistent fused SNN (int8 tensor cores).
// 128 CTAs x 512 threads; warp grid wm in {0,1} x wn in {0..7}.
// ---------------------------------------------------------------------------
__global__ void __launch_bounds__(THREADS, 1) snn_kernel(const float* __restrict__ b2g,
                                                         const float* __restrict__ b3g,
                                                         float* __restrict__ outp) {
    extern __shared__ char sm[];
    const uint32_t smb = smem_u32(sm);
    const int tid  = threadIdx.x;
    const int warp = tid >> 5;
    const int lane = tid & 31;
    const int wm   = warp >> 3;        // 0..1
    const int wn   = warp & 7;         // 0..7
    const int row0 = blockIdx.x * 64;

    // scales (exact same formulas as quant_kernel)
    const float d1_2 = __uint_as_float(g_maxbits[0]) * (1.0f / 127.0f);
    const float d2_2 = d1_2 * (1.0f / 254.0f);
    const float d1_3 = __uint_as_float(g_maxbits[1]) * (1.0f / 127.0f);
    const float d2_3 = d1_3 * (1.0f / 254.0f);

    // ldmatrix lane addressing (identical byte structure to the bf16 path)
    const int rowl_a = (lane & 7) + ((lane >> 3) & 1) * 8;
    const int sega   = ((lane >> 4) & 1) * 16;           // bytes
    const int rowl_b = (lane & 7) + ((lane >> 4) & 1) * 8;
    const int segb   = ((lane >> 3) & 1) * 16;           // bytes

    const uint32_t aS1 = smb + S1_OFF + (uint32_t)(wm * 32 + rowl_a) * S1B + sega;
    const uint32_t aS2 = smb + S2_OFF + (uint32_t)(wm * 32 + rowl_a) * WBB + sega;
    const uint32_t bOff = (uint32_t)(wn * 16 + rowl_b) * WBB + segb;

    // ---- zero membranes for this tile ----
    const float4 z4 = make_float4(0.f, 0.f, 0.f, 0.f);
    #pragma unroll
    for (int q = 0; q < 16; ++q) {
        size_t gi = (size_t)row0 * HID + (size_t)(q * THREADS + tid) * 4;
        *(float4*)(g_m1 + gi) = z4;
        *(float4*)(g_m2 + gi) = z4;
    }
    __syncthreads();

    load_tile(0, 0, tid, sm);

    int acc3A[2][2][4] = {};      // persistent GEMM3 accumulators (exact int)
    int acc3B[2][2][4] = {};
    int acczA[2][2][4] = {};      // per-chunk GEMM2 accumulators
    int acczB[2][2][4] = {};

    #pragma unroll 1
    for (int step = 0; step < T_STEPS; ++step) {
        // ======== LIF layer 1 -> s1 (int8 {0,1}) ========
        #pragma unroll 4
        for (int i = 0; i < 16; ++i) {
            int l = i * THREADS + tid;             // float4 index 0..8191
            size_t gi = (size_t)row0 * HID + (size_t)l * 4;
            float4 z = *(const float4*)(g_z1 + gi);
            float4 m = *(float4*)(g_m1 + gi);
            uint32_t sx, sy, sz, sw;
            m.x = BETA_F * m.x + z.x; if (m.x >= 1.0f) { m.x -= 1.0f; sx = 1u; } else sx = 0u;
            m.y = BETA_F * m.y + z.y; if (m.y >= 1.0f) { m.y -= 1.0f; sy = 1u; } else sy = 0u;
            m.z = BETA_F * m.z + z.z; if (m.z >= 1.0f) { m.z -= 1.0f; sz = 1u; } else sz = 0u;
            m.w = BETA_F * m.w + z.w; if (m.w >= 1.0f) { m.w -= 1.0f; sw = 1u; } else sw = 0u;
            *(float4*)(g_m1 + gi) = m;
            int lr = (l * 4) >> 9;                 // local row
            int lc = (l * 4) & 511;                // element (=byte) offset, mult of 4
            *(uint32_t*)(sm + S1_OFF + lr * S1B + lc) =
                sx | (sy << 8) | (sz << 16) | (sw << 24);
        }

        // ======== 20 ring tiles: per chunk 4x GEMM2, epilogue, 1x GEMM3 ========
        #pragma unroll 1
        for (int t = 0; t < 20; ++t) {
            const int c = t / 5, r = t - c * 5;
            const int gt = step * 20 + t;
            const uint32_t ringb = smb + WB_OFF + (uint32_t)(gt & 1) * TILE_SZ;

            cp_wait<0>();
            __syncthreads();             // tile gt resident; prev buffer free; s1/s2 visible
            if (gt + 1 < T_STEPS * 20) load_tile((t + 1) % 20, (gt + 1) & 1, tid, sm);

            if (r < 4) {
                mma_k128_i8<S1B>(acczA, acczB, aS1 + (uint32_t)(r * 128), ringb + bOff);
            } else {
                // ---- epilogue: z2 = d1*accA + d2*accB + b2 -> LIF2 -> s2 ----
                const int rbase = wm * 32 + (lane >> 2);
                const int cloc0 = wn * 16 + (lane & 3) * 2;
                #pragma unroll
                for (int nb = 0; nb < 2; ++nb) {
                    const int cloc = cloc0 + nb * 8;
                    const int col  = c * 128 + cloc;
                    const float2 bb = *(const float2*)(b2g + col);
                    #pragma unroll
                    for (int mb = 0; mb < 2; ++mb)
                    #pragma unroll
                    for (int h = 0; h < 2; ++h) {
                        const int row = rbase + mb * 16 + h * 8;
                        float* m2p = g_m2 + (size_t)(row0 + row) * HID + col;
                        float2 m = *(float2*)m2p;
                        float zx = fmaf(d1_2, (float)acczA[mb][nb][h * 2 + 0],
                                   fmaf(d2_2, (float)acczB[mb][nb][h * 2 + 0], bb.x));
                        float zy = fmaf(d1_2, (float)acczA[mb][nb][h * 2 + 1],
                                   fmaf(d2_2, (float)acczB[mb][nb][h * 2 + 1], bb.y));
                        m.x = BETA_F * m.x + zx;
                        m.y = BETA_F * m.y + zy;
                        uint32_t s0, s1v;
                        if (m.x >= 1.0f) { m.x -= 1.0f; s0 = 1u; } else s0 = 0u;
                        if (m.y >= 1.0f) { m.y -= 1.0f; s1v = 1u; } else s1v = 0u;
                        *(float2*)m2p = m;
                        *(uint16_t*)(sm + S2_OFF + row * WBB + cloc) =
                            (uint16_t)(s0 | (s1v << 8));
                        acczA[mb][nb][h * 2 + 0] = 0; acczA[mb][nb][h * 2 + 1] = 0;
                        acczB[mb][nb][h * 2 + 0] = 0; acczB[mb][nb][h * 2 + 1] = 0;
                    }
                }
                __syncthreads();         // s2 visible to all warps

                mma_k128_i8<WBB>(acc3A, acc3B, aS2, ringb + bOff);
            }
        }
    }

    // ======== Final output: out = (d1*acc3A + d2*acc3B)/T + b3 ========
    const float sA = d1_3 * (1.0f / (float)T_STEPS);
    const float sB = d2_3 * (1.0f / (float)T_STEPS);
    const int rbase = wm * 32 + (lane >> 2);
    const int cb = wn * 16 + (lane & 3) * 2;
    #pragma unroll
    for (int nb = 0; nb < 2; ++nb) {
        const int col = cb + nb * 8;
        const float2 bb = *(const float2*)(b3g + col);
        #pragma unroll
        for (int mb = 0; mb < 2; ++mb)
        #pragma unroll
        for (int h = 0; h < 2; ++h) {
            const int row = row0 + rbase + mb * 16 + h * 8;
            float2 v;
            v.x = fmaf(sA, (float)acc3A[mb][nb][h * 2 + 0],
                  fmaf(sB, (float)acc3B[mb][nb][h * 2 + 0], bb.x));
            v.y = fmaf(sA, (float)acc3A[mb][nb][h * 2 + 1],
                  fmaf(sB, (float)acc3B[mb][nb][h * 2 + 1], bb.y));
            *(float2*)(outp + (size_t)row * NOUT + col) = v;
        }
    }
}

// ---------------------------------------------------------------------------
// Launch
// ---------------------------------------------------------------------------
extern "C" void kernel_launch(void* const* d_in, const int* in_sizes, int n_in,
                              void* d_out, int out_size) {
    (void)in_sizes; (void)n_in; (void)out_size;
    const float* x  = (const float*)d_in[0];
    const float* W1 = (const float*)d_in[1];
    const float* b1 = (const float*)d_in[2];
    const float* W2 = (const float*)d_in[3];
    const float* b2 = (const float*)d_in[4];
    const float* W3 = (const float*)d_in[5];
    const float* b3 = (const float*)d_in[6];
    float* out = (float*)d_out;

    zero_kernel<<<1, 1>>>();
    max_kernel<<<256, 256>>>(W2, W3);

    const int nconv = HID * HID + NOUT * HID;
    quant_kernel<<<(nconv + 255) / 256, 256>>>(W2, W3);

    dim3 zgrid(HID / 64, BATCH / 64);
    z1_kernel<<<zgrid, 256>>>(x, W1, b1);

    cudaFuncSetAttribute(snn_kernel, cudaFuncAttributeMaxDynamicSharedMemorySize, SMEM_TOTAL);
    snn_kernel<<<BATCH / 64, THREADS, SMEM_TOTAL>>>(b2, b3, out);
}